// round 1
// baseline (speedup 1.0000x reference)
#include <cuda_runtime.h>
#include <math.h>

#define S_LEN 512
#define HID   256
#define NH    8
#define HD    32
#define SCALE_F 0.17677669529663687f   // 1/sqrt(32)
#define PI_F    3.14159265358979323846f

// Scratch (no allocations allowed): qkv projections + attention context
__device__ float g_qkv[3 * S_LEN * HID];
__device__ float g_ctx[S_LEN * HID];

typedef unsigned long long ull;

__device__ __forceinline__ ull pack2(float lo, float hi) {
    ull r; asm("mov.b64 %0, {%1, %2};" : "=l"(r) : "f"(lo), "f"(hi)); return r;
}
__device__ __forceinline__ void unpack2(ull v, float& lo, float& hi) {
    asm("mov.b64 {%0, %1}, %2;" : "=f"(lo), "=f"(hi) : "l"(v));
}
#define FMA2(d, a, b, c) asm("fma.rn.f32x2 %0, %1, %2, %3;" : "=l"(d) : "l"(a), "l"(b), "l"(c))
#define MUL2(d, a, b)    asm("mul.rn.f32x2 %0, %1, %2;"     : "=l"(d) : "l"(a), "l"(b))
#define ADD2(d, a, b)    asm("add.rn.f32x2 %0, %1, %2;"     : "=l"(d) : "l"(a), "l"(b))

// ---------------------------------------------------------------------------
// Tiled fp32 GEMM: C[m,n] = bias[n] + sum_c A[m,c] * W[n,c]   (A:[M,K], W:[N,K])
// BM=BN=64, BK=16, 256 threads, 4x4 per thread.
// ---------------------------------------------------------------------------
#define BM 64
#define BN 64
#define BK 16

__device__ __forceinline__ void gemm_body(
    const float* __restrict__ A, const float* __restrict__ W,
    const float* __restrict__ bias, float* __restrict__ C,
    int M, int N, int K)
{
    __shared__ float As[BK][BM + 1];
    __shared__ float Ws[BK][BN + 1];
    const int tid = threadIdx.x;
    const int m0 = blockIdx.y * BM;
    const int n0 = blockIdx.x * BN;
    const int tm = tid >> 4;          // 0..15
    const int tn = tid & 15;          // 0..15
    const int lr = tid >> 2;          // 0..63
    const int lc = (tid & 3) << 2;    // 0,4,8,12

    float acc[4][4];
#pragma unroll
    for (int i = 0; i < 4; i++)
#pragma unroll
        for (int j = 0; j < 4; j++) acc[i][j] = 0.0f;

    const float* Ap = A + (m0 + lr) * K + lc;
    const float* Wp = W + (n0 + lr) * K + lc;

    for (int k0 = 0; k0 < K; k0 += BK) {
        float4 a4 = *reinterpret_cast<const float4*>(Ap + k0);
        float4 w4 = *reinterpret_cast<const float4*>(Wp + k0);
        As[lc + 0][lr] = a4.x; As[lc + 1][lr] = a4.y;
        As[lc + 2][lr] = a4.z; As[lc + 3][lr] = a4.w;
        Ws[lc + 0][lr] = w4.x; Ws[lc + 1][lr] = w4.y;
        Ws[lc + 2][lr] = w4.z; Ws[lc + 3][lr] = w4.w;
        __syncthreads();
#pragma unroll
        for (int kk = 0; kk < BK; kk++) {
            float ar[4], wr[4];
#pragma unroll
            for (int i = 0; i < 4; i++) ar[i] = As[kk][tm * 4 + i];
#pragma unroll
            for (int j = 0; j < 4; j++) wr[j] = Ws[kk][tn * 4 + j];
#pragma unroll
            for (int i = 0; i < 4; i++)
#pragma unroll
                for (int j = 0; j < 4; j++)
                    acc[i][j] = fmaf(ar[i], wr[j], acc[i][j]);
        }
        __syncthreads();
    }

#pragma unroll
    for (int i = 0; i < 4; i++) {
        int m = m0 + tm * 4 + i;
        float4 o;
        o.x = acc[i][0] + bias[n0 + tn * 4 + 0];
        o.y = acc[i][1] + bias[n0 + tn * 4 + 1];
        o.z = acc[i][2] + bias[n0 + tn * 4 + 2];
        o.w = acc[i][3] + bias[n0 + tn * 4 + 3];
        *reinterpret_cast<float4*>(&C[m * N + n0 + tn * 4]) = o;
    }
}

__global__ void __launch_bounds__(256)
gemm_qkv_kernel(const float* __restrict__ x,
                const float* __restrict__ wq, const float* __restrict__ bq,
                const float* __restrict__ wk, const float* __restrict__ bk,
                const float* __restrict__ wv, const float* __restrict__ bv)
{
    const int z = blockIdx.z;
    const float* W = (z == 0) ? wq : ((z == 1) ? wk : wv);
    const float* b = (z == 0) ? bq : ((z == 1) ? bk : bv);
    float* C = g_qkv + z * (S_LEN * HID);
    gemm_body(x, W, b, C, S_LEN, HID, HID);
}

__global__ void __launch_bounds__(256)
gemm_out_kernel(const float* __restrict__ wo, const float* __restrict__ bo,
                float* __restrict__ out)
{
    gemm_body(g_ctx, wo, bo, out, S_LEN, HID, HID);
}

// ---------------------------------------------------------------------------
// Attention kernel. Grid: (64 i-tiles, 8 heads), 256 threads = 8 i-rows x 32 d.
// For each (h,i,d): logit(j) = K0*cos(theta_j), theta_j = omega*(i-j)+phi.
// Maintain phasors (K0*cos, K0*sin) for even/odd j packed in f32x2, rotate by
// 2*omega per step. exp via degree-4 Taylor (|z| <= 0.177). V staged in smem
// as [d][j] (stride 514 floats, 8B aligned for LDS.64).
// ---------------------------------------------------------------------------
#define VSTRIDE 514
#define ATTN_SMEM (HD * VSTRIDE * 4)   // 65792 bytes

__global__ void __launch_bounds__(256)
attn_kernel()
{
    extern __shared__ float Vs[];   // [32][514]
    const int h   = blockIdx.y;
    const int tid = threadIdx.x;
    const int d   = tid & 31;
    const int r   = tid >> 5;
    const int i   = blockIdx.x * 8 + r;

    const float* gq = g_qkv;
    const float* gk = g_qkv + S_LEN * HID;
    const float* gv = g_qkv + 2 * S_LEN * HID;

    // Stage V[h, :, :] -> Vs[d][j]. float4 along d (coalesced 128B gmem reads).
    {
        const int d4 = tid & 7;    // which 4-dim group
        const int j0 = tid >> 3;   // 0..31
#pragma unroll
        for (int t = 0; t < 16; t++) {
            int j = j0 + t * 32;
            float4 v4 = *reinterpret_cast<const float4*>(gv + j * HID + h * HD + d4 * 4);
            Vs[(d4 * 4 + 0) * VSTRIDE + j] = v4.x;
            Vs[(d4 * 4 + 1) * VSTRIDE + j] = v4.y;
            Vs[(d4 * 4 + 2) * VSTRIDE + j] = v4.z;
            Vs[(d4 * 4 + 3) * VSTRIDE + j] = v4.w;
        }
    }

    // Per-thread wave parameters
    const int col = h * HD + d;
    const float qv = gq[i * HID + col];
    const float kv = gk[i * HID + col];
    const float vv = gv[i * HID + col];

    const float omega = PI_F / (1.0f + expf(-qv));   // sigmoid(q)*pi
    const float amp   = 1.0f / (1.0f + expf(-kv));   // sigmoid(k)
    const float phase = PI_F * tanhf(vv);            // tanh(v)*pi
    const float K0    = SCALE_F * amp;

    const float th0 = omega * (float)i + phase;      // theta at j=0
    float s0, c0, swv, cwv;
    sincosf(th0, &s0, &c0);
    sincosf(omega, &swv, &cwv);
    // theta at j=1 = th0 - omega
    const float c1 = c0 * cwv + s0 * swv;
    const float s1 = s0 * cwv - c0 * swv;
    // rotation step: -2*omega
    const float c2 = cwv * cwv - swv * swv;
    const float s2 = 2.0f * swv * cwv;

    ull X   = pack2(K0 * c0, K0 * c1);
    ull Y   = pack2(K0 * s0, K0 * s1);
    ull C2  = pack2(c2, c2);
    ull S2  = pack2(s2, s2);
    ull NS2 = pack2(-s2, -s2);
    ull P4  = pack2(1.0f / 24.0f, 1.0f / 24.0f);
    ull P3  = pack2(1.0f / 6.0f, 1.0f / 6.0f);
    ull P2  = pack2(0.5f, 0.5f);
    ull P1  = pack2(1.0f, 1.0f);
    ull acc  = 0ull;   // (0.f, 0.f)
    ull sumw = 0ull;

    __syncthreads();

    const ull* vp = reinterpret_cast<const ull*>(Vs + d * VSTRIDE);

#pragma unroll 8
    for (int k = 0; k < 256; k++) {
        ull V2 = vp[k];
        // exp(z), z = X (already includes K0*cos):  deg-4 Taylor Horner
        ull p;
        FMA2(p, X, P4, P3);
        FMA2(p, p, X, P2);
        FMA2(p, p, X, P1);
        FMA2(p, p, X, P1);
        ADD2(sumw, sumw, p);
        FMA2(acc, p, V2, acc);
        // rotate phasor by -2*omega
        ull t1, t2;
        MUL2(t1, Y, S2);
        MUL2(t2, X, NS2);
        FMA2(X, X, C2, t1);
        FMA2(Y, Y, C2, t2);
    }

    float ae, ao, se, so;
    unpack2(acc, ae, ao);
    unpack2(sumw, se, so);
    g_ctx[i * HID + col] = (ae + ao) / (se + so);
}

// ---------------------------------------------------------------------------
extern "C" void kernel_launch(void* const* d_in, const int* in_sizes, int n_in,
                              void* d_out, int out_size)
{
    const float* x  = (const float*)d_in[0];
    const float* wq = (const float*)d_in[1];
    const float* bq = (const float*)d_in[2];
    const float* wk = (const float*)d_in[3];
    const float* bk = (const float*)d_in[4];
    const float* wv = (const float*)d_in[5];
    const float* bv = (const float*)d_in[6];
    const float* wo = (const float*)d_in[7];
    const float* bo = (const float*)d_in[8];
    float* out = (float*)d_out;

    // QKV projections: one launch, z selects q/k/v
    gemm_qkv_kernel<<<dim3(HID / BN, S_LEN / BM, 3), 256>>>(x, wq, bq, wk, bk, wv, bv);

    // Attention (needs >48KB dynamic smem)
    cudaFuncSetAttribute(attn_kernel, cudaFuncAttributeMaxDynamicSharedMemorySize, ATTN_SMEM);
    attn_kernel<<<dim3(S_LEN / 8, NH), 256, ATTN_SMEM>>>();

    // Output projection
    gemm_out_kernel<<<dim3(HID / BN, S_LEN / BM), 256>>>(wo, bo, out);
}

// round 6
// speedup vs baseline: 1.1422x; 1.1422x over previous
#include <cuda_runtime.h>
#include <math.h>

#define S_LEN 512
#define HID   256
#define NH    8
#define HD    32
#define SCALE_F 0.17677669529663687f   // 1/sqrt(32)
#define PI_F    3.14159265358979323846f

// Scratch (no allocations allowed): qkv projections + attention context
__device__ float g_qkv[3 * S_LEN * HID];
__device__ float g_ctx[S_LEN * HID];

typedef unsigned long long ull;

__device__ __forceinline__ ull pack2(float lo, float hi) {
    ull r; asm("mov.b64 %0, {%1, %2};" : "=l"(r) : "f"(lo), "f"(hi)); return r;
}
__device__ __forceinline__ void unpack2(ull v, float& lo, float& hi) {
    asm("mov.b64 {%0, %1}, %2;" : "=f"(lo), "=f"(hi) : "l"(v));
}
#define FMA2(d, a, b, c) asm("fma.rn.f32x2 %0, %1, %2, %3;" : "=l"(d) : "l"(a), "l"(b), "l"(c))
#define ADD2(d, a, b)    asm("add.rn.f32x2 %0, %1, %2;"     : "=l"(d) : "l"(a), "l"(b))
#define XOR64(d, a, b)   asm("xor.b64 %0, %1, %2;"          : "=l"(d) : "l"(a), "l"(b))

// ---------------------------------------------------------------------------
// Tiled fp32 GEMM: C[m,n] = bias[n] + sum_c A[m,c] * W[n,c]   (A:[M,256], W:[N,256])
// BM=BN=32, BK=32, 256 threads, 4 outputs/thread (1 row x 4 cols as 2 f32x2).
// Grid per GEMM: (N/32) x (M/32) -> 128 blocks (vs 32 before): latency hidden.
// ---------------------------------------------------------------------------
#define GK 256

__device__ __forceinline__ void gemm_body(
    const float* __restrict__ A, const float* __restrict__ W,
    const float* __restrict__ bias, float* __restrict__ C)
{
    __shared__ float As[32][33];   // [k][m]
    __shared__ float Ws[32][36];   // [k][n]  (row = 144B -> 16B-aligned f4 reads)

    const int tid = threadIdx.x;
    const int m0 = blockIdx.y * 32;
    const int n0 = blockIdx.x * 32;
    const int tm = tid >> 3;        // 0..31 output row
    const int tn = tid & 7;         // 0..7  -> cols 4tn..4tn+3
    const int lr = tid >> 3;        // staging row 0..31
    const int lk = (tid & 7) << 2;  // staging k 0,4,..28

    const float* Ap = A + (m0 + lr) * GK + lk;
    const float* Wp = W + (n0 + lr) * GK + lk;

    ull acc0 = 0ull, acc1 = 0ull;

    float4 a4 = *reinterpret_cast<const float4*>(Ap);
    float4 w4 = *reinterpret_cast<const float4*>(Wp);

#pragma unroll 1
    for (int it = 0; it < 8; it++) {
        __syncthreads();
        As[lk + 0][lr] = a4.x; As[lk + 1][lr] = a4.y;
        As[lk + 2][lr] = a4.z; As[lk + 3][lr] = a4.w;
        Ws[lk + 0][lr] = w4.x; Ws[lk + 1][lr] = w4.y;
        Ws[lk + 2][lr] = w4.z; Ws[lk + 3][lr] = w4.w;
        __syncthreads();
        if (it < 7) {
            a4 = *reinterpret_cast<const float4*>(Ap + (it + 1) * 32);
            w4 = *reinterpret_cast<const float4*>(Wp + (it + 1) * 32);
        }
#pragma unroll
        for (int kk = 0; kk < 32; kk++) {
            float a = As[kk][tm];
            ull A2 = pack2(a, a);
            const ull* wrow = reinterpret_cast<const ull*>(&Ws[kk][tn * 4]);
            ull w0 = wrow[0], w1 = wrow[1];
            FMA2(acc0, A2, w0, acc0);
            FMA2(acc1, A2, w1, acc1);
        }
    }

    float4 b4 = *reinterpret_cast<const float4*>(bias + n0 + tn * 4);
    float o0, o1, o2, o3;
    unpack2(acc0, o0, o1);
    unpack2(acc1, o2, o3);
    float4 o; o.x = o0 + b4.x; o.y = o1 + b4.y; o.z = o2 + b4.z; o.w = o3 + b4.w;
    *reinterpret_cast<float4*>(&C[(m0 + tm) * HID + n0 + tn * 4]) = o;
}

__global__ void __launch_bounds__(256)
gemm_qkv_kernel(const float* __restrict__ x,
                const float* __restrict__ wq, const float* __restrict__ bq,
                const float* __restrict__ wk, const float* __restrict__ bk,
                const float* __restrict__ wv, const float* __restrict__ bv)
{
    const int z = blockIdx.z;
    const float* W = (z == 0) ? wq : ((z == 1) ? wk : wv);
    const float* b = (z == 0) ? bq : ((z == 1) ? bk : bv);
    float* C = g_qkv + z * (S_LEN * HID);
    gemm_body(x, W, b, C);
}

__global__ void __launch_bounds__(256)
gemm_out_kernel(const float* __restrict__ wo, const float* __restrict__ bo,
                float* __restrict__ out)
{
    gemm_body(g_ctx, wo, bo, out);
}

// ---------------------------------------------------------------------------
// Attention. Grid: (64 i-tiles, 8 heads), 256 threads = 8 i-rows x 32 d.
// logit(j) = X_j = K0*cos(omega*(i-j)+phase), K0 = SCALE*sigmoid(k) <= 0.177.
// Even/odd j packed in f32x2. Chebyshev recurrence (step 2*omega):
//   X_{k+1} = 2cos(2w)*X_k - X_{k-1}   -> 1 FMA2 + 1 xor (sign flip, alu pipe)
// exp(X) via deg-3 Taylor (abs err <= 4.6e-5; same-sign in num & denom).
// V in smem as [jpair][d] ull: lanes read consecutive 8B -> conflict-free.
// ---------------------------------------------------------------------------
#define ATTN_SMEM (256 * 32 * 8)   // 65536 bytes: 256 j-pairs x 32 d x ull

__global__ void __launch_bounds__(256)
attn_kernel()
{
    extern __shared__ ull Vs[];    // [256][32]
    const int h   = blockIdx.y;
    const int tid = threadIdx.x;
    const int d   = tid & 31;
    const int r   = tid >> 5;      // warp id = i-row
    const int i   = blockIdx.x * 8 + r;

    const float* gq = g_qkv;
    const float* gk = g_qkv + S_LEN * HID;
    const float* gv = g_qkv + 2 * S_LEN * HID;

    // Stage V[h,:,:]: Vs[k][d] = (v[2k,d], v[2k+1,d]). Coalesced 128B gmem rows,
    // conflict-free STS (lanes consecutive 8B).
    {
        const int g = tid >> 5;    // 0..7
#pragma unroll 4
        for (int kk = 0; kk < 32; kk++) {
            int k = g * 32 + kk;
            float v0 = gv[(2 * k)     * HID + h * HD + d];
            float v1 = gv[(2 * k + 1) * HID + h * HD + d];
            Vs[k * 32 + d] = pack2(v0, v1);
        }
    }

    // Per-thread wave parameters
    const int col = h * HD + d;
    const float qv = gq[i * HID + col];
    const float kv = gk[i * HID + col];
    const float vv = gv[i * HID + col];

    const float omega = PI_F / (1.0f + expf(-qv));   // sigmoid(q)*pi
    const float amp   = 1.0f / (1.0f + expf(-kv));   // sigmoid(k)
    const float phase = PI_F * tanhf(vv);            // tanh(v)*pi
    const float K0    = SCALE_F * amp;

    const float th0 = omega * (float)i + phase;      // theta at j=0
    float s0, c0, sw, cw;
    sincosf(th0, &s0, &c0);
    sincosf(omega, &sw, &cw);
    const float c2w = cw * cw - sw * sw;             // cos(2w)
    const float s2w = 2.0f * sw * cw;                // sin(2w)
    // X_0 lanes: j=0 -> theta0 ; j=1 -> theta0 - w
    const float x0e = K0 * c0;
    const float x0o = K0 * (c0 * cw + s0 * sw);
    // X_{-1} lanes: theta0 + 2w ; theta0 + w
    const float xme = K0 * (c0 * c2w - s0 * s2w);
    const float xmo = K0 * (c0 * cw - s0 * sw);

    ull X    = pack2(x0e, x0o);
    ull NX   = pack2(-xme, -xmo);                    // -X_{k-1}
    ull C2   = pack2(2.0f * c2w, 2.0f * c2w);
    const ull SMASK = 0x8000000080000000ULL;
    ull P6   = pack2(1.0f / 6.0f, 1.0f / 6.0f);
    ull P2   = pack2(0.5f, 0.5f);
    ull ONE  = pack2(1.0f, 1.0f);
    ull acc  = 0ull;
    ull sumw = 0ull;

    __syncthreads();

    const ull* vp = Vs + d;

#pragma unroll 8
    for (int k = 0; k < 256; k++) {
        ull V2 = vp[k * 32];
        // exp(X) ~ ((X/6 + 1/2)X + 1)X + 1
        ull p;
        FMA2(p, X, P6, P2);
        FMA2(p, p, X, ONE);
        FMA2(p, p, X, ONE);
        ADD2(sumw, sumw, p);
        FMA2(acc, p, V2, acc);
        // Chebyshev: X_{k+1} = 2cos(2w)*X_k + (-X_{k-1})
        ull Xn;
        FMA2(Xn, C2, X, NX);
        XOR64(NX, X, SMASK);      // alu pipe, off the fma class
        X = Xn;
    }

    float ae, ao, se, so;
    unpack2(acc, ae, ao);
    unpack2(sumw, se, so);
    g_ctx[i * HID + col] = (ae + ao) / (se + so);
}

// ---------------------------------------------------------------------------
extern "C" void kernel_launch(void* const* d_in, const int* in_sizes, int n_in,
                              void* d_out, int out_size)
{
    const float* x  = (const float*)d_in[0];
    const float* wq = (const float*)d_in[1];
    const float* bq = (const float*)d_in[2];
    const float* wk = (const float*)d_in[3];
    const float* bk = (const float*)d_in[4];
    const float* wv = (const float*)d_in[5];
    const float* bv = (const float*)d_in[6];
    const float* wo = (const float*)d_in[7];
    const float* bo = (const float*)d_in[8];
    float* out = (float*)d_out;

    // QKV projections: grid (8 n) x (16 m) x 3 = 384 blocks
    gemm_qkv_kernel<<<dim3(HID / 32, S_LEN / 32, 3), 256>>>(x, wq, bq, wk, bk, wv, bv);

    // Attention (64KB dynamic smem)
    cudaFuncSetAttribute(attn_kernel, cudaFuncAttributeMaxDynamicSharedMemorySize, ATTN_SMEM);
    attn_kernel<<<dim3(S_LEN / 8, NH), 256, ATTN_SMEM>>>();

    // Output projection: 128 blocks
    gemm_out_kernel<<<dim3(HID / 32, S_LEN / 32), 256>>>(wo, bo, out);
}

// round 7
// speedup vs baseline: 1.3468x; 1.1791x over previous
#include <cuda_runtime.h>
#include <math.h>

#define S_LEN 512
#define HID   256
#define NH    8
#define HD    32
#define SCALE_F 0.17677669529663687f   // 1/sqrt(32)
#define PI_F    3.14159265358979323846f

// Scratch (no allocations allowed): qkv projections + attention context
__device__ float g_qkv[3 * S_LEN * HID];
__device__ float g_ctx[S_LEN * HID];

typedef unsigned long long ull;

__device__ __forceinline__ ull pack2(float lo, float hi) {
    ull r; asm("mov.b64 %0, {%1, %2};" : "=l"(r) : "f"(lo), "f"(hi)); return r;
}
__device__ __forceinline__ void unpack2(ull v, float& lo, float& hi) {
    asm("mov.b64 {%0, %1}, %2;" : "=f"(lo), "=f"(hi) : "l"(v));
}
#define FMA2(d, a, b, c) asm("fma.rn.f32x2 %0, %1, %2, %3;" : "=l"(d) : "l"(a), "l"(b), "l"(c))
#define MUL2(d, a, b)    asm("mul.rn.f32x2 %0, %1, %2;"     : "=l"(d) : "l"(a), "l"(b))
#define ADD2(d, a, b)    asm("add.rn.f32x2 %0, %1, %2;"     : "=l"(d) : "l"(a), "l"(b))
#define XOR64(d, a, b)   asm("xor.b64 %0, %1, %2;"          : "=l"(d) : "l"(a), "l"(b))

// ---------------------------------------------------------------------------
// GEMM: C[m,n] = bias[n] + sum_c A[m,c]*W[n,c].  A:[M,256] W:[N,256] C ld=256.
// Tile 32x32, BK=32, 128 threads, 2 rows x 4 cols per thread.
// A staged as pre-splatted (a,a) f32x2 pairs so the inner loop is
// 2x LDS.64 + 1x LDS.128 + 4x FMA2  (7 issues vs 8 fma-pipe cycles: fma-bound).
// ---------------------------------------------------------------------------
#define GK 256

__device__ __forceinline__ void gemm_body(
    const float* __restrict__ A, const float* __restrict__ W,
    const float* __restrict__ bias, float* __restrict__ C)
{
    __shared__ ull   As2[32][33];   // [k][m] -> (a,a) pairs, 8448 B
    __shared__ float Ws [32][36];   // [k][n], rows 144 B (16B aligned)

    const int tid = threadIdx.x;       // 0..127
    const int m0 = blockIdx.y * 32;
    const int n0 = blockIdx.x * 32;
    const int r  = tid >> 3;           // 0..15
    const int c  = tid & 7;            // 0..7

    const float* Ap = A + (m0 + r) * GK + 4 * c;
    const float* Wp = W + (n0 + r) * GK + 4 * c;

    ull acc00 = 0ull, acc01 = 0ull, acc10 = 0ull, acc11 = 0ull;

    float4 a4a = *reinterpret_cast<const float4*>(Ap);
    float4 a4b = *reinterpret_cast<const float4*>(Ap + 16 * GK);
    float4 w4a = *reinterpret_cast<const float4*>(Wp);
    float4 w4b = *reinterpret_cast<const float4*>(Wp + 16 * GK);

#pragma unroll 1
    for (int it = 0; it < 8; it++) {
        __syncthreads();
        As2[4*c + 0][r]      = pack2(a4a.x, a4a.x);
        As2[4*c + 1][r]      = pack2(a4a.y, a4a.y);
        As2[4*c + 2][r]      = pack2(a4a.z, a4a.z);
        As2[4*c + 3][r]      = pack2(a4a.w, a4a.w);
        As2[4*c + 0][16 + r] = pack2(a4b.x, a4b.x);
        As2[4*c + 1][16 + r] = pack2(a4b.y, a4b.y);
        As2[4*c + 2][16 + r] = pack2(a4b.z, a4b.z);
        As2[4*c + 3][16 + r] = pack2(a4b.w, a4b.w);
        Ws[4*c + 0][r]      = w4a.x; Ws[4*c + 1][r]      = w4a.y;
        Ws[4*c + 2][r]      = w4a.z; Ws[4*c + 3][r]      = w4a.w;
        Ws[4*c + 0][16 + r] = w4b.x; Ws[4*c + 1][16 + r] = w4b.y;
        Ws[4*c + 2][16 + r] = w4b.z; Ws[4*c + 3][16 + r] = w4b.w;
        __syncthreads();
        if (it < 7) {
            a4a = *reinterpret_cast<const float4*>(Ap + (it + 1) * 32);
            a4b = *reinterpret_cast<const float4*>(Ap + 16 * GK + (it + 1) * 32);
            w4a = *reinterpret_cast<const float4*>(Wp + (it + 1) * 32);
            w4b = *reinterpret_cast<const float4*>(Wp + 16 * GK + (it + 1) * 32);
        }
#pragma unroll
        for (int kk = 0; kk < 32; kk++) {
            ull a0 = As2[kk][2 * r];
            ull a1 = As2[kk][2 * r + 1];
            const ull* wr = reinterpret_cast<const ull*>(&Ws[kk][4 * c]);
            ull w01 = wr[0], w23 = wr[1];
            FMA2(acc00, a0, w01, acc00);
            FMA2(acc01, a0, w23, acc01);
            FMA2(acc10, a1, w01, acc10);
            FMA2(acc11, a1, w23, acc11);
        }
    }

    float4 b4 = *reinterpret_cast<const float4*>(bias + n0 + 4 * c);
    float x0, x1, x2, x3;
    unpack2(acc00, x0, x1); unpack2(acc01, x2, x3);
    {
        float4 o; o.x = x0 + b4.x; o.y = x1 + b4.y; o.z = x2 + b4.z; o.w = x3 + b4.w;
        *reinterpret_cast<float4*>(&C[(m0 + 2*r) * HID + n0 + 4*c]) = o;
    }
    unpack2(acc10, x0, x1); unpack2(acc11, x2, x3);
    {
        float4 o; o.x = x0 + b4.x; o.y = x1 + b4.y; o.z = x2 + b4.z; o.w = x3 + b4.w;
        *reinterpret_cast<float4*>(&C[(m0 + 2*r + 1) * HID + n0 + 4*c]) = o;
    }
}

__global__ void __launch_bounds__(128)
gemm_qkv_kernel(const float* __restrict__ x,
                const float* __restrict__ wq, const float* __restrict__ bq,
                const float* __restrict__ wk, const float* __restrict__ bk,
                const float* __restrict__ wv, const float* __restrict__ bv)
{
    const int z = blockIdx.z;
    const float* W = (z == 0) ? wq : ((z == 1) ? wk : wv);
    const float* b = (z == 0) ? bq : ((z == 1) ? bk : bv);
    float* C = g_qkv + z * (S_LEN * HID);
    gemm_body(x, W, b, C);
}

__global__ void __launch_bounds__(128)
gemm_out_kernel(const float* __restrict__ wo, const float* __restrict__ bo,
                float* __restrict__ out)
{
    gemm_body(g_ctx, wo, bo, out);
}

// ---------------------------------------------------------------------------
// Attention. Grid: (64 i-tiles, 8 heads), 256 threads = 8 i-rows x 32 d.
// logit X_j = K0*cos(theta0 - j*omega), K0 = SCALE*sigmoid(k) <= 0.177.
// Even/odd j packed in f32x2; Chebyshev recurrence (step 2w).
// Weight p = 1 + X + X^2/2 + X^3/6 (deg-3 Taylor of exp, |X|<=0.177).
// Hot loop computes acc = sum (p-1)*V = sum (X*r)*V with r = 1 + X/2 + X^2/6
// (5 fma-class ops per j-pair). sum V precomputed in staging; denominator
// sum_j p(X_j) via closed-form Dirichlet sums of cos(m*theta_j), m=1,2,3.
// ---------------------------------------------------------------------------
#define ATTN_SMEM (256 * 32 * 8 + 8 * 32 * 8)   // V pairs + partial sums

__global__ void __launch_bounds__(256)
attn_kernel()
{
    extern __shared__ ull Vs[];           // [256][32] j-pairs, then Ps[8][32]
    ull* Ps = Vs + 256 * 32;
    const int h   = blockIdx.y;
    const int tid = threadIdx.x;
    const int d   = tid & 31;
    const int r   = tid >> 5;             // warp id = i-row
    const int i   = blockIdx.x * 8 + r;

    const float* gq = g_qkv;
    const float* gk = g_qkv + S_LEN * HID;
    const float* gv = g_qkv + 2 * S_LEN * HID;

    // Stage V[h,:,:] as (even,odd) pairs + per-group partial sums of V.
    {
        float sve = 0.0f, svo = 0.0f;
#pragma unroll 4
        for (int kk = 0; kk < 32; kk++) {
            int k = r * 32 + kk;
            float v0 = gv[(2 * k)     * HID + h * HD + d];
            float v1 = gv[(2 * k + 1) * HID + h * HD + d];
            Vs[k * 32 + d] = pack2(v0, v1);
            sve += v0; svo += v1;
        }
        Ps[r * 32 + d] = pack2(sve, svo);
    }

    // Per-thread wave parameters (no smem: overlaps other warps' staging)
    const int col = h * HD + d;
    const float qv = gq[i * HID + col];
    const float kv = gk[i * HID + col];
    const float vv = gv[i * HID + col];

    const float omega = PI_F / (1.0f + expf(-qv));   // sigmoid(q)*pi
    const float amp   = 1.0f / (1.0f + expf(-kv));   // sigmoid(k)
    const float phase = PI_F * tanhf(vv);            // tanh(v)*pi
    const float K0    = SCALE_F * amp;

    const float th0 = omega * (float)i + phase;      // theta at j=0
    float s0, c0, sw, cw;
    sincosf(th0, &s0, &c0);
    sincosf(omega, &sw, &cw);
    const float c2w = cw * cw - sw * sw;             // cos(2w)
    const float s2w = 2.0f * sw * cw;                // sin(2w)
    // X_0 lanes: j=0, j=1 ; X_{-1} lanes: j=-2, j=-1
    const float x0e = K0 * c0;
    const float x0o = K0 * (c0 * cw + s0 * sw);
    const float xme = K0 * (c0 * c2w - s0 * s2w);
    const float xmo = K0 * (c0 * cw - s0 * sw);

    // ---- closed-form denominator: sumw = sum_j p(K0 cos(th0 - j w)), j=0..511
    // Dm = sum_j cos(m*th0 - j*m*w) = cos(m*th0 - 255.5*m*w) * sin(256*m*w)/sin(m*w/2)
    float sumw;
    {
        const float a = th0, b = omega;
        float sb2 = sinf(0.5f * b);
        float D1 = cosf(a - 255.5f * b) * sinf(256.0f * b) / sb2;
        float D2 = cosf(2.0f * a - 511.0f * b) * sinf(512.0f * b) / sw;
        float D3;
        float s3h = sinf(1.5f * b);
        if (fabsf(s3h) > 1e-3f) {
            D3 = cosf(3.0f * a - 766.5f * b) * sinf(768.0f * b) / s3h;
        } else {
            // near pole 1.5w ~= k*pi: sinc fallback (512*k is even)
            float kf  = rintf(1.5f * b * (1.0f / PI_F));
            float dlt = 1.5f * b - kf * PI_F;
            float sgn = (((int)kf) & 1) ? -1.0f : 1.0f;
            float rr  = (fabsf(dlt) > 1e-12f) ? (sinf(512.0f * dlt) / dlt) : 512.0f;
            D3 = cosf(3.0f * a - 766.5f * b) * rr * sgn;
        }
        float S1 = K0 * D1;
        float S2 = K0 * K0 * (256.0f + 0.5f * D2);
        float S3 = K0 * K0 * K0 * (0.75f * D1 + 0.25f * D3);
        sumw = 512.0f + S1 + 0.5f * S2 + (1.0f / 6.0f) * S3;
    }

    ull X    = pack2(x0e, x0o);
    ull NX   = pack2(-xme, -xmo);                    // -X_{k-1}
    ull C2   = pack2(2.0f * c2w, 2.0f * c2w);
    const ull SMASK = 0x8000000080000000ULL;
    ull P6   = pack2(1.0f / 6.0f, 1.0f / 6.0f);
    ull P2   = pack2(0.5f, 0.5f);
    ull ONE  = pack2(1.0f, 1.0f);
    ull acc  = 0ull;

    __syncthreads();

    // sum of V over all j for this (h,d)
    float svE = 0.0f, svO = 0.0f;
#pragma unroll
    for (int g = 0; g < 8; g++) {
        float pe, po;
        unpack2(Ps[g * 32 + d], pe, po);
        svE += pe; svO += po;
    }

    const ull* vp = Vs + d;

#pragma unroll 8
    for (int k = 0; k < 256; k++) {
        ull V2 = vp[k * 32];
        ull rr, t, Xn;
        // r = (X/6 + 1/2)*X + 1 ;  (p-1) = X*r
        FMA2(rr, X, P6, P2);
        FMA2(rr, rr, X, ONE);
        MUL2(t, X, V2);
        FMA2(acc, rr, t, acc);
        // Chebyshev: X_{k+1} = 2cos(2w)*X_k + (-X_{k-1})
        FMA2(Xn, C2, X, NX);
        XOR64(NX, X, SMASK);      // alu pipe
        X = Xn;
    }

    float ae, ao;
    unpack2(acc, ae, ao);
    g_ctx[i * HID + col] = (svE + svO + ae + ao) / sumw;
}

// ---------------------------------------------------------------------------
extern "C" void kernel_launch(void* const* d_in, const int* in_sizes, int n_in,
                              void* d_out, int out_size)
{
    const float* x  = (const float*)d_in[0];
    const float* wq = (const float*)d_in[1];
    const float* bq = (const float*)d_in[2];
    const float* wk = (const float*)d_in[3];
    const float* bk = (const float*)d_in[4];
    const float* wv = (const float*)d_in[5];
    const float* bv = (const float*)d_in[6];
    const float* wo = (const float*)d_in[7];
    const float* bo = (const float*)d_in[8];
    float* out = (float*)d_out;

    // QKV projections: (8 n) x (16 m) x 3 = 384 blocks of 128 threads
    gemm_qkv_kernel<<<dim3(HID / 32, S_LEN / 32, 3), 128>>>(x, wq, bq, wk, bk, wv, bv);

    // Attention
    cudaFuncSetAttribute(attn_kernel, cudaFuncAttributeMaxDynamicSharedMemorySize, ATTN_SMEM);
    attn_kernel<<<dim3(S_LEN / 8, NH), 256, ATTN_SMEM>>>();

    // Output projection: 128 blocks
    gemm_out_kernel<<<dim3(HID / 32, S_LEN / 32), 128>>>(wo, bo, out);
}